// round 4
// baseline (speedup 1.0000x reference)
#include <cuda_runtime.h>
#include <cstdint>
#include <cstdio>

// ---------------------------------------------------------------------------
// Modified MHA (no input proj) + dual output projections.
//   B=16, L=S=1024, E=512, H=8, hd=64. fp32 in/out, TF32 tensor-core math.
// Stage 1: flash attention -> g_attn (B,L,E) fp32 scratch (__device__ global).
// Stage 2: out1 = attn @ W1^T + b1 ; out2 = attn @ W2^T + b2 -> d_out (2,B,L,E)
// ---------------------------------------------------------------------------

#define BB 16
#define LL 1024
#define SS 1024
#define EE 512
#define HH 8
#define HD 64

// 33.5 MB scratch for attention output (allowed: static __device__ array)
__device__ float g_attn[(size_t)BB * LL * EE];

// ---- helpers --------------------------------------------------------------

__device__ __forceinline__ uint32_t f2tf32(float x) {
    uint32_t r;
    asm volatile("cvt.rna.tf32.f32 %0, %1;" : "=r"(r) : "f"(x));
    return r;
}

// mma.sync m16n8k8 tf32: A row-major 16x8, B col-major 8x8, C/D fp32 16x8.
// Fragment layout (g = lane>>2, t = lane&3):
//   a0=A[g][t]  a1=A[g+8][t]  a2=A[g][t+4]  a3=A[g+8][t+4]
//   b0=B[k=t][n=g]  b1=B[k=t+4][n=g]
//   c0=C[g][2t] c1=C[g][2t+1] c2=C[g+8][2t] c3=C[g+8][2t+1]
__device__ __forceinline__ void mma_tf32(float c[4],
                                         uint32_t a0, uint32_t a1, uint32_t a2, uint32_t a3,
                                         uint32_t b0, uint32_t b1) {
    asm volatile(
        "mma.sync.aligned.m16n8k8.row.col.f32.tf32.tf32.f32 "
        "{%0,%1,%2,%3}, {%4,%5,%6,%7}, {%8,%9}, {%0,%1,%2,%3};\n"
        : "+f"(c[0]), "+f"(c[1]), "+f"(c[2]), "+f"(c[3])
        : "r"(a0), "r"(a1), "r"(a2), "r"(a3), "r"(b0), "r"(b1));
}

// ---- Kernel 1: flash attention ---------------------------------------------
// Block = 128 threads (4 warps). Each block: one (b,h), 64 query rows.
// Warp w owns query rows [w*16, w*16+16). S streamed in 64-row tiles.

#define SQ_STRIDE 68   // pad so fragment LDS is conflict-free
#define SK_STRIDE 68
#define SV_STRIDE 72   // (stride mod 32)==8 -> conflict-free PV b-frag loads
#define SP_STRIDE 68

#define ATTN_SMEM ((64*SQ_STRIDE + 64*SK_STRIDE + 64*SV_STRIDE + 64*SP_STRIDE) * 4)

__global__ void __launch_bounds__(128)
attn_kernel(const float* __restrict__ q,
            const float* __restrict__ kmat,
            const float* __restrict__ vmat)
{
    extern __shared__ float sm1[];
    float* sQ = sm1;                       // [64][68]
    float* sK = sQ + 64 * SQ_STRIDE;       // [64][68]
    float* sV = sK + 64 * SK_STRIDE;       // [64][72]
    float* sP = sV + 64 * SV_STRIDE;       // [64][68]

    const int tid  = threadIdx.x;
    const int warp = tid >> 5;
    const int lane = tid & 31;
    const int g = lane >> 2;   // group id 0..7
    const int t = lane & 3;    // thread-in-group 0..3

    const int ltile = blockIdx.x;  // 0..15
    const int h     = blockIdx.y;  // 0..7
    const int b     = blockIdx.z;  // 0..15

    const float scaling = 0.125f;  // hd^-0.5

    // ---- load Q tile (64 x 64), pre-scaled, tf32-rounded ----
    {
        const float* qbase = q + ((size_t)b * LL + (size_t)ltile * 64) * EE + h * HD;
        #pragma unroll
        for (int i = tid; i < 64 * 16; i += 128) {
            int row = i >> 4;
            int c4  = (i & 15) * 4;
            float4 val = *reinterpret_cast<const float4*>(qbase + (size_t)row * EE + c4);
            float* dst = sQ + row * SQ_STRIDE + c4;
            dst[0] = __uint_as_float(f2tf32(val.x * scaling));
            dst[1] = __uint_as_float(f2tf32(val.y * scaling));
            dst[2] = __uint_as_float(f2tf32(val.z * scaling));
            dst[3] = __uint_as_float(f2tf32(val.w * scaling));
        }
    }

    float m_prev[2] = {-1e30f, -1e30f};
    float l_sum[2]  = {0.f, 0.f};
    float acc_o[8][4];
    #pragma unroll
    for (int n = 0; n < 8; n++)
        #pragma unroll
        for (int i = 0; i < 4; i++) acc_o[n][i] = 0.f;

    const float* kbase = kmat + (size_t)b * SS * EE + h * HD;
    const float* vbase = vmat + (size_t)b * SS * EE + h * HD;

    for (int st = 0; st < SS; st += 64) {
        __syncthreads();  // previous iteration's sK/sV reads done (also covers sQ load 1st iter)

        // ---- load K,V tiles (64 x 64 each), tf32-rounded ----
        #pragma unroll
        for (int i = tid; i < 64 * 16; i += 128) {
            int row = i >> 4;
            int c4  = (i & 15) * 4;
            float4 kv = *reinterpret_cast<const float4*>(kbase + (size_t)(st + row) * EE + c4);
            float* dk = sK + row * SK_STRIDE + c4;
            dk[0] = __uint_as_float(f2tf32(kv.x));
            dk[1] = __uint_as_float(f2tf32(kv.y));
            dk[2] = __uint_as_float(f2tf32(kv.z));
            dk[3] = __uint_as_float(f2tf32(kv.w));
            float4 vv = *reinterpret_cast<const float4*>(vbase + (size_t)(st + row) * EE + c4);
            float* dv = sV + row * SV_STRIDE + c4;
            dv[0] = __uint_as_float(f2tf32(vv.x));
            dv[1] = __uint_as_float(f2tf32(vv.y));
            dv[2] = __uint_as_float(f2tf32(vv.z));
            dv[3] = __uint_as_float(f2tf32(vv.w));
        }
        __syncthreads();

        // ---- scores = Qtile @ Ktile^T : warp rows [warp*16,+16), cols 0..63 ----
        float sc[8][4];
        #pragma unroll
        for (int n = 0; n < 8; n++) { sc[n][0] = sc[n][1] = sc[n][2] = sc[n][3] = 0.f; }

        #pragma unroll
        for (int kk = 0; kk < 8; kk++) {
            const float* qa = sQ + (warp * 16) * SQ_STRIDE + kk * 8;
            uint32_t a0 = __float_as_uint(qa[g * SQ_STRIDE + t]);
            uint32_t a1 = __float_as_uint(qa[(g + 8) * SQ_STRIDE + t]);
            uint32_t a2 = __float_as_uint(qa[g * SQ_STRIDE + t + 4]);
            uint32_t a3 = __float_as_uint(qa[(g + 8) * SQ_STRIDE + t + 4]);
            #pragma unroll
            for (int n = 0; n < 8; n++) {
                // B[k=d][n=s] = K[s][d]
                const float* kb = sK + (n * 8 + g) * SK_STRIDE + kk * 8;
                uint32_t b0 = __float_as_uint(kb[t]);
                uint32_t b1 = __float_as_uint(kb[t + 4]);
                mma_tf32(sc[n], a0, a1, a2, a3, b0, b1);
            }
        }

        // ---- online softmax (rows r0=g, r1=g+8 of this warp's 16) ----
        float mt0 = -1e30f, mt1 = -1e30f;
        #pragma unroll
        for (int n = 0; n < 8; n++) {
            mt0 = fmaxf(mt0, fmaxf(sc[n][0], sc[n][1]));
            mt1 = fmaxf(mt1, fmaxf(sc[n][2], sc[n][3]));
        }
        #pragma unroll
        for (int o = 1; o <= 2; o <<= 1) {
            mt0 = fmaxf(mt0, __shfl_xor_sync(0xffffffffu, mt0, o));
            mt1 = fmaxf(mt1, __shfl_xor_sync(0xffffffffu, mt1, o));
        }
        float mn0 = fmaxf(m_prev[0], mt0);
        float mn1 = fmaxf(m_prev[1], mt1);
        float alpha0 = __expf(m_prev[0] - mn0);
        float alpha1 = __expf(m_prev[1] - mn1);
        m_prev[0] = mn0; m_prev[1] = mn1;

        float rs0 = 0.f, rs1 = 0.f;
        float* pw = sP + (warp * 16) * SP_STRIDE;
        #pragma unroll
        for (int n = 0; n < 8; n++) {
            float p00 = __expf(sc[n][0] - mn0);
            float p01 = __expf(sc[n][1] - mn0);
            float p10 = __expf(sc[n][2] - mn1);
            float p11 = __expf(sc[n][3] - mn1);
            rs0 += p00 + p01;
            rs1 += p10 + p11;
            int col = n * 8 + 2 * t;
            pw[g * SP_STRIDE + col]           = __uint_as_float(f2tf32(p00));
            pw[g * SP_STRIDE + col + 1]       = __uint_as_float(f2tf32(p01));
            pw[(g + 8) * SP_STRIDE + col]     = __uint_as_float(f2tf32(p10));
            pw[(g + 8) * SP_STRIDE + col + 1] = __uint_as_float(f2tf32(p11));
        }
        #pragma unroll
        for (int o = 1; o <= 2; o <<= 1) {
            rs0 += __shfl_xor_sync(0xffffffffu, rs0, o);
            rs1 += __shfl_xor_sync(0xffffffffu, rs1, o);
        }
        l_sum[0] = l_sum[0] * alpha0 + rs0;
        l_sum[1] = l_sum[1] * alpha1 + rs1;
        #pragma unroll
        for (int n = 0; n < 8; n++) {
            acc_o[n][0] *= alpha0; acc_o[n][1] *= alpha0;
            acc_o[n][2] *= alpha1; acc_o[n][3] *= alpha1;
        }
        __syncwarp();  // sP written by this warp, read by this warp below

        // ---- acc_o += P(16x64) @ V(64x64) ----
        #pragma unroll
        for (int kk = 0; kk < 8; kk++) {
            const float* pa = sP + (warp * 16) * SP_STRIDE + kk * 8;
            uint32_t a0 = __float_as_uint(pa[g * SP_STRIDE + t]);
            uint32_t a1 = __float_as_uint(pa[(g + 8) * SP_STRIDE + t]);
            uint32_t a2 = __float_as_uint(pa[g * SP_STRIDE + t + 4]);
            uint32_t a3 = __float_as_uint(pa[(g + 8) * SP_STRIDE + t + 4]);
            const float* vb = sV + (kk * 8) * SV_STRIDE;
            #pragma unroll
            for (int n = 0; n < 8; n++) {
                // B[k=s][n=d] = V[s][d]
                uint32_t b0 = __float_as_uint(vb[t * SV_STRIDE + n * 8 + g]);
                uint32_t b1 = __float_as_uint(vb[(t + 4) * SV_STRIDE + n * 8 + g]);
                mma_tf32(acc_o[n], a0, a1, a2, a3, b0, b1);
            }
        }
    }

    // ---- epilogue: normalize + write attn(b,l,e) ----
    float inv0 = 1.f / l_sum[0];
    float inv1 = 1.f / l_sum[1];
    float* obase = g_attn + ((size_t)b * LL + (size_t)ltile * 64 + warp * 16) * EE + h * HD;
    #pragma unroll
    for (int n = 0; n < 8; n++) {
        int col = n * 8 + 2 * t;
        float2 v0 = make_float2(acc_o[n][0] * inv0, acc_o[n][1] * inv0);
        float2 v1 = make_float2(acc_o[n][2] * inv1, acc_o[n][3] * inv1);
        *reinterpret_cast<float2*>(obase + (size_t)g * EE + col)       = v0;
        *reinterpret_cast<float2*>(obase + (size_t)(g + 8) * EE + col) = v1;
    }
}

// ---- Kernel 2: dual output projection --------------------------------------
// out_i[m][n] = sum_k attn[m][k] * W_i[n][k] + bias_i[n],  m in [0,16384), n in [0,512)
// Block: 128 threads, tile 64(m) x 64(n), both weights resident (attn read once).

#define SA_STRIDE 68
#define SW_STRIDE 68
#define PROJ_SMEM ((64*SA_STRIDE + 2*64*SW_STRIDE) * 4)

__global__ void __launch_bounds__(128)
proj_kernel(const float* __restrict__ w1, const float* __restrict__ bias1,
            const float* __restrict__ w2, const float* __restrict__ bias2,
            float* __restrict__ out)
{
    extern __shared__ float sm2[];
    float* sA  = sm2;                      // [64][68]
    float* sW1 = sA + 64 * SA_STRIDE;      // [64][68]  (row = n_local, col = k_local)
    float* sW2 = sW1 + 64 * SW_STRIDE;     // [64][68]

    const int tid  = threadIdx.x;
    const int warp = tid >> 5;
    const int lane = tid & 31;
    const int g = lane >> 2;
    const int t = lane & 3;

    const int mt = blockIdx.x;   // 0..255
    const int nt = blockIdx.y;   // 0..7

    const float* abase  = g_attn + (size_t)mt * 64 * EE;
    const float* w1base = w1 + (size_t)nt * 64 * EE;
    const float* w2base = w2 + (size_t)nt * 64 * EE;

    float acc1[8][4], acc2[8][4];
    #pragma unroll
    for (int n = 0; n < 8; n++)
        #pragma unroll
        for (int i = 0; i < 4; i++) { acc1[n][i] = 0.f; acc2[n][i] = 0.f; }

    for (int k0 = 0; k0 < EE; k0 += 64) {
        __syncthreads();
        #pragma unroll
        for (int i = tid; i < 64 * 16; i += 128) {
            int row = i >> 4;
            int c4  = (i & 15) * 4;
            float4 av = *reinterpret_cast<const float4*>(abase + (size_t)row * EE + k0 + c4);
            float* da = sA + row * SA_STRIDE + c4;
            da[0] = __uint_as_float(f2tf32(av.x));
            da[1] = __uint_as_float(f2tf32(av.y));
            da[2] = __uint_as_float(f2tf32(av.z));
            da[3] = __uint_as_float(f2tf32(av.w));
            float4 wv = *reinterpret_cast<const float4*>(w1base + (size_t)row * EE + k0 + c4);
            float* dw = sW1 + row * SW_STRIDE + c4;
            dw[0] = __uint_as_float(f2tf32(wv.x));
            dw[1] = __uint_as_float(f2tf32(wv.y));
            dw[2] = __uint_as_float(f2tf32(wv.z));
            dw[3] = __uint_as_float(f2tf32(wv.w));
            float4 wv2 = *reinterpret_cast<const float4*>(w2base + (size_t)row * EE + k0 + c4);
            float* dw2 = sW2 + row * SW_STRIDE + c4;
            dw2[0] = __uint_as_float(f2tf32(wv2.x));
            dw2[1] = __uint_as_float(f2tf32(wv2.y));
            dw2[2] = __uint_as_float(f2tf32(wv2.z));
            dw2[3] = __uint_as_float(f2tf32(wv2.w));
        }
        __syncthreads();

        #pragma unroll
        for (int kk = 0; kk < 8; kk++) {
            const float* aa = sA + (warp * 16) * SA_STRIDE + kk * 8;
            uint32_t a0 = __float_as_uint(aa[g * SA_STRIDE + t]);
            uint32_t a1 = __float_as_uint(aa[(g + 8) * SA_STRIDE + t]);
            uint32_t a2 = __float_as_uint(aa[g * SA_STRIDE + t + 4]);
            uint32_t a3 = __float_as_uint(aa[(g + 8) * SA_STRIDE + t + 4]);
            #pragma unroll
            for (int n = 0; n < 8; n++) {
                const float* wb1 = sW1 + (n * 8 + g) * SW_STRIDE + kk * 8;
                uint32_t b0 = __float_as_uint(wb1[t]);
                uint32_t b1 = __float_as_uint(wb1[t + 4]);
                mma_tf32(acc1[n], a0, a1, a2, a3, b0, b1);
                const float* wb2 = sW2 + (n * 8 + g) * SW_STRIDE + kk * 8;
                uint32_t c0 = __float_as_uint(wb2[t]);
                uint32_t c1 = __float_as_uint(wb2[t + 4]);
                mma_tf32(acc2[n], a0, a1, a2, a3, c0, c1);
            }
        }
    }

    // ---- epilogue: bias + store both outputs ----
    const size_t out_off = ((size_t)mt * 64 + warp * 16) * EE + (size_t)nt * 64;
    float* o1 = out + out_off;
    float* o2 = out + (size_t)BB * LL * EE + out_off;
    #pragma unroll
    for (int n = 0; n < 8; n++) {
        int col = n * 8 + 2 * t;
        float ba1 = __ldg(bias1 + nt * 64 + col);
        float bb1 = __ldg(bias1 + nt * 64 + col + 1);
        float ba2 = __ldg(bias2 + nt * 64 + col);
        float bb2 = __ldg(bias2 + nt * 64 + col + 1);
        *reinterpret_cast<float2*>(o1 + (size_t)g * EE + col) =
            make_float2(acc1[n][0] + ba1, acc1[n][1] + bb1);
        *reinterpret_cast<float2*>(o1 + (size_t)(g + 8) * EE + col) =
            make_float2(acc1[n][2] + ba1, acc1[n][3] + bb1);
        *reinterpret_cast<float2*>(o2 + (size_t)g * EE + col) =
            make_float2(acc2[n][0] + ba2, acc2[n][1] + bb2);
        *reinterpret_cast<float2*>(o2 + (size_t)(g + 8) * EE + col) =
            make_float2(acc2[n][2] + ba2, acc2[n][3] + bb2);
    }
}

// ---- launch -----------------------------------------------------------------

extern "C" void kernel_launch(void* const* d_in, const int* in_sizes, int n_in,
                              void* d_out, int out_size) {
    (void)in_sizes; (void)n_in; (void)out_size;
    const float* q  = (const float*)d_in[0];
    const float* k  = (const float*)d_in[1];
    const float* v  = (const float*)d_in[2];
    const float* w1 = (const float*)d_in[3];
    const float* b1 = (const float*)d_in[4];
    const float* w2 = (const float*)d_in[5];
    const float* b2 = (const float*)d_in[6];
    float* out = (float*)d_out;

    // dynamic smem > 48KB needs opt-in (idempotent, capture-safe: not stream-ordered)
    cudaFuncSetAttribute((const void*)attn_kernel,
                         cudaFuncAttributeMaxDynamicSharedMemorySize, ATTN_SMEM);
    cudaFuncSetAttribute((const void*)proj_kernel,
                         cudaFuncAttributeMaxDynamicSharedMemorySize, PROJ_SMEM);

    dim3 grid1(LL / 64, HH, BB);   // (16, 8, 16)
    attn_kernel<<<grid1, 128, ATTN_SMEM>>>(q, k, v);

    dim3 grid2((BB * LL) / 64, EE / 64);  // (256, 8)
    proj_kernel<<<grid2, 128, PROJ_SMEM>>>(w1, b1, w2, b2, out);
}